// round 2
// baseline (speedup 1.0000x reference)
#include <cuda_runtime.h>
#include <cuda_bf16.h>
#include <cstdint>

#define N_ROWS 8192
#define DIM    1024
#define MARGIN 0.3f

// ---------------- device scratch (no allocations allowed) ----------------
__device__ __nv_bfloat16 g_xn[N_ROWS * DIM];   // 16 MB
__device__ __nv_bfloat16 g_yn[N_ROWS * DIM];   // 16 MB
__device__ float g_rowsum[N_ROWS];             // sum_j exp(S[i,j]) incl diag
__device__ float g_colsum[N_ROWS];             // sum_i exp(S[i,j]) incl diag
__device__ float g_diag[N_ROWS];               // S[i,i] in fp32 (from GEMM accum)

// ---------------- kernel 1: normalize rows, emit bf16, zero accumulators ----
__global__ void __launch_bounds__(256) normalize_kernel(const float* __restrict__ x,
                                                        const float* __restrict__ y) {
    int bid = blockIdx.x;
    int row = bid & (N_ROWS - 1);
    bool isx = bid < N_ROWS;
    const float* src = (isx ? x : y) + (size_t)row * DIM;
    __nv_bfloat16* dst = (isx ? g_xn : g_yn) + (size_t)row * DIM;

    if (threadIdx.x == 0 && isx) {
        g_rowsum[row] = 0.0f;
        g_colsum[row] = 0.0f;
    }

    const float4* s4 = (const float4*)src;
    float4 v = s4[threadIdx.x];
    float ss = v.x * v.x + v.y * v.y + v.z * v.z + v.w * v.w;

    #pragma unroll
    for (int o = 16; o > 0; o >>= 1) ss += __shfl_xor_sync(0xffffffffu, ss, o);
    __shared__ float sw[8];
    int warp = threadIdx.x >> 5, lane = threadIdx.x & 31;
    if (lane == 0) sw[warp] = ss;
    __syncthreads();
    float tot = 0.0f;
    #pragma unroll
    for (int w = 0; w < 8; w++) tot += sw[w];

    float scale = 1.0f / fmaxf(sqrtf(tot), 1e-8f);
    __nv_bfloat162* d2 = (__nv_bfloat162*)dst;
    d2[2 * threadIdx.x + 0] = __floats2bfloat162_rn(v.x * scale, v.y * scale);
    d2[2 * threadIdx.x + 1] = __floats2bfloat162_rn(v.z * scale, v.w * scale);
}

// ---------------- kernel 2: fused GEMM + exp + row/col reductions -----------
// S = xn @ yn^T ; BM=128, BN=256, BK=32, 2-stage cp.async pipeline.
// 8 warps as 2(m) x 4(n), warp tile 64x64 via mma.sync m16n8k16 bf16.
#define BM 128
#define BN 256
#define BK 32
#define SPAD 40   // padded smem row stride (elems); 80 B rows -> 16B aligned, conflict-free
#define ASZ (BM * SPAD)
#define BSZ (BN * SPAD)
#define SMEM_BYTES ((ASZ + BSZ) * 2 /*stages*/ * 2 /*bytes*/)

__device__ __forceinline__ void mma_bf16(float* c, const uint32_t* a, const uint32_t* b) {
    asm volatile(
        "mma.sync.aligned.m16n8k16.row.col.f32.bf16.bf16.f32 "
        "{%0,%1,%2,%3}, {%4,%5,%6,%7}, {%8,%9}, {%0,%1,%2,%3};\n"
        : "+f"(c[0]), "+f"(c[1]), "+f"(c[2]), "+f"(c[3])
        : "r"(a[0]), "r"(a[1]), "r"(a[2]), "r"(a[3]), "r"(b[0]), "r"(b[1]));
}

__device__ __forceinline__ void cp16(__nv_bfloat16* dst, const __nv_bfloat16* src) {
    uint32_t d = (uint32_t)__cvta_generic_to_shared(dst);
    asm volatile("cp.async.cg.shared.global [%0], [%1], 16;\n" :: "r"(d), "l"(src));
}

__global__ void __launch_bounds__(256, 1) gemm_loss_kernel() {
    extern __shared__ __nv_bfloat16 sm[];
    __nv_bfloat16* Asb[2] = { sm, sm + ASZ };
    __nv_bfloat16* Bsb[2] = { sm + 2 * ASZ, sm + 2 * ASZ + BSZ };

    const int bm = blockIdx.y, bn = blockIdx.x;
    const int tid = threadIdx.x;
    const int lane = tid & 31, warp = tid >> 5;
    const int wm = (warp & 1) * 64;   // warp m offset (2 x 64 = 128)
    const int wn = (warp >> 1) * 64;  // warp n offset (4 x 64 = 256)
    const int g = lane >> 2;          // groupID 0..7
    const int q = lane & 3;           // quad    0..3

    float acc[4][8][4];
    #pragma unroll
    for (int mi = 0; mi < 4; mi++)
        #pragma unroll
        for (int ni = 0; ni < 8; ni++)
            #pragma unroll
            for (int v = 0; v < 4; v++) acc[mi][ni][v] = 0.0f;

    const __nv_bfloat16* Ag = g_xn + (size_t)(bm * BM) * DIM;
    const __nv_bfloat16* Bg = g_yn + (size_t)(bn * BN) * DIM;

    // ---- async stage loader: BK=32 elems = 64 B per row, 4 chunks of 16 B ----
    auto load_stage = [&](int buf, int kt) {
        __nv_bfloat16* As = Asb[buf];
        __nv_bfloat16* Bs = Bsb[buf];
        #pragma unroll
        for (int i = 0; i < 2; i++) {            // A: 128 rows * 4 chunks = 512
            int id = tid + i * 256;
            int r = id >> 2, c = (id & 3) * 8;
            cp16(As + r * SPAD + c, Ag + (size_t)r * DIM + kt + c);
        }
        #pragma unroll
        for (int i = 0; i < 4; i++) {            // B: 256 rows * 4 chunks = 1024
            int id = tid + i * 256;
            int r = id >> 2, c = (id & 3) * 8;
            cp16(Bs + r * SPAD + c, Bg + (size_t)r * DIM + kt + c);
        }
    };

    auto compute_stage = [&](int buf) {
        const __nv_bfloat16* As = Asb[buf];
        const __nv_bfloat16* Bs = Bsb[buf];
        #pragma unroll
        for (int s = 0; s < 2; s++) {
            const int kk = s * 16;
            uint32_t af[4][4], bf[8][2];
            #pragma unroll
            for (int mi = 0; mi < 4; mi++) {
                const __nv_bfloat16* base = As + (wm + mi * 16 + g) * SPAD + kk + q * 2;
                af[mi][0] = *(const uint32_t*)(base);
                af[mi][1] = *(const uint32_t*)(base + 8 * SPAD);
                af[mi][2] = *(const uint32_t*)(base + 8);
                af[mi][3] = *(const uint32_t*)(base + 8 * SPAD + 8);
            }
            #pragma unroll
            for (int ni = 0; ni < 8; ni++) {
                const __nv_bfloat16* base = Bs + (wn + ni * 8 + g) * SPAD + kk + q * 2;
                bf[ni][0] = *(const uint32_t*)(base);
                bf[ni][1] = *(const uint32_t*)(base + 8);
            }
            #pragma unroll
            for (int mi = 0; mi < 4; mi++)
                #pragma unroll
                for (int ni = 0; ni < 8; ni++)
                    mma_bf16(acc[mi][ni], af[mi], bf[ni]);
        }
    };

    // ---- 2-stage pipeline over 32 K-tiles ----
    const int NK = DIM / BK;
    int buf = 0;
    load_stage(0, 0);
    asm volatile("cp.async.commit_group;\n");
    for (int it = 0; it < NK; it++) {
        if (it + 1 < NK) load_stage(buf ^ 1, (it + 1) * BK);
        asm volatile("cp.async.commit_group;\n");
        asm volatile("cp.async.wait_group 1;\n");
        __syncthreads();
        compute_stage(buf);
        buf ^= 1;
        __syncthreads();
    }

    // ---- diagonal extraction (pre-exp) for tiles crossed by the diagonal ----
    // global row R = bm*128 + r,   global col C = bn*256 + c ; diag when R == C
    {
        int off = -1;
        if (bm == 2 * bn) off = 0;
        else if (bm == 2 * bn + 1) off = 128;
        if (off >= 0) {
            #pragma unroll
            for (int mi = 0; mi < 4; mi++)
                #pragma unroll
                for (int ni = 0; ni < 8; ni++)
                    #pragma unroll
                    for (int v = 0; v < 4; v++) {
                        int r = wm + mi * 16 + g + (v >> 1) * 8;
                        int c = wn + ni * 8 + q * 2 + (v & 1);
                        if (c == r + off) g_diag[bm * BM + r] = acc[mi][ni][v];
                    }
        }
    }

    // ---- epilogue: exp, then row/col partial sums ----
    #pragma unroll
    for (int mi = 0; mi < 4; mi++)
        #pragma unroll
        for (int ni = 0; ni < 8; ni++)
            #pragma unroll
            for (int v = 0; v < 4; v++) acc[mi][ni][v] = __expf(acc[mi][ni][v]);

    // row sums: row = wm+mi*16+g+h*8 ; reduce over ni and quad lanes
    #pragma unroll
    for (int mi = 0; mi < 4; mi++) {
        #pragma unroll
        for (int h = 0; h < 2; h++) {
            float p = 0.0f;
            #pragma unroll
            for (int ni = 0; ni < 8; ni++) p += acc[mi][ni][2 * h] + acc[mi][ni][2 * h + 1];
            p += __shfl_xor_sync(0xffffffffu, p, 1);
            p += __shfl_xor_sync(0xffffffffu, p, 2);
            if (q == 0)
                atomicAdd(&g_rowsum[bm * BM + wm + mi * 16 + g + h * 8], p);
        }
    }
    // col sums: col = wn+ni*8+q*2+h ; reduce over mi and group lanes
    #pragma unroll
    for (int ni = 0; ni < 8; ni++) {
        #pragma unroll
        for (int h = 0; h < 2; h++) {
            float p = 0.0f;
            #pragma unroll
            for (int mi = 0; mi < 4; mi++) p += acc[mi][ni][h] + acc[mi][ni][h + 2];
            p += __shfl_xor_sync(0xffffffffu, p, 4);
            p += __shfl_xor_sync(0xffffffffu, p, 8);
            p += __shfl_xor_sync(0xffffffffu, p, 16);
            if (g == 0)
                atomicAdd(&g_colsum[bn * BN + wn + ni * 8 + q * 2 + h], p);
        }
    }
}

// ---------------- kernel 3: final loss ---------------------------------------
__global__ void __launch_bounds__(1024) final_kernel(float* __restrict__ out) {
    double s = 0.0;
    for (int i = threadIdx.x; i < N_ROWS; i += 1024) {
        float d = g_diag[i];
        float ed = expf(d);
        float m1 = expf(d - MARGIN);
        float negr = g_rowsum[i] - ed;
        float negc = g_colsum[i] - ed;
        s += (double)log1pf(negr / m1) + (double)log1pf(negc / m1);
    }
    #pragma unroll
    for (int o = 16; o > 0; o >>= 1) s += __shfl_xor_sync(0xffffffffu, s, o);
    __shared__ double sw[32];
    int warp = threadIdx.x >> 5, lane = threadIdx.x & 31;
    if (lane == 0) sw[warp] = s;
    __syncthreads();
    if (threadIdx.x == 0) {
        double t = 0.0;
        #pragma unroll
        for (int w = 0; w < 32; w++) t += sw[w];
        out[0] = (float)(t / (double)N_ROWS);
    }
}

// ---------------- launch --------------------------------------------------
extern "C" void kernel_launch(void* const* d_in, const int* in_sizes, int n_in,
                              void* d_out, int out_size) {
    const float* x = (const float*)d_in[0];
    const float* y = (const float*)d_in[1];
    float* out = (float*)d_out;

    cudaFuncSetAttribute(gemm_loss_kernel,
                         cudaFuncAttributeMaxDynamicSharedMemorySize, SMEM_BYTES);

    normalize_kernel<<<2 * N_ROWS, 256>>>(x, y);
    dim3 grid(N_ROWS / BN, N_ROWS / BM);
    gemm_loss_kernel<<<grid, 256, SMEM_BYTES>>>();
    final_kernel<<<1, 1024>>>(out);
}

// round 5
// speedup vs baseline: 1.3370x; 1.3370x over previous
#include <cuda_runtime.h>
#include <cuda_bf16.h>
#include <cuda_fp8.h>
#include <cstdint>

#define N_ROWS 8192
#define DIM    1024
#define MARGIN 0.3f
#define FP8_SCALE 16.0f
#define INV_S2    (1.0f / 256.0f)   // 1/(16*16)

// ---------------- device scratch ----------------
__device__ uint8_t g_x8[N_ROWS * DIM];   // 8 MB, e4m3, normalized * 16
__device__ uint8_t g_y8[N_ROWS * DIM];   // 8 MB
__device__ float g_rowsum[N_ROWS];
__device__ float g_colsum[N_ROWS];
__device__ float g_diag[N_ROWS];         // scaled-back fp32 diag from GEMM accum

// ---------------- kernel 1: normalize -> e4m3 (x16), zero accumulators ------
__global__ void __launch_bounds__(256) normalize_kernel(const float* __restrict__ x,
                                                        const float* __restrict__ y) {
    int bid = blockIdx.x;
    int row = bid & (N_ROWS - 1);
    bool isx = bid < N_ROWS;
    const float* src = (isx ? x : y) + (size_t)row * DIM;
    uint8_t* dst = (isx ? g_x8 : g_y8) + (size_t)row * DIM;

    if (threadIdx.x == 0 && isx) { g_rowsum[row] = 0.0f; g_colsum[row] = 0.0f; }

    const float4* s4 = (const float4*)src;
    float4 v = s4[threadIdx.x];
    float ss = v.x * v.x + v.y * v.y + v.z * v.z + v.w * v.w;
    #pragma unroll
    for (int o = 16; o > 0; o >>= 1) ss += __shfl_xor_sync(0xffffffffu, ss, o);
    __shared__ float sw[8];
    int warp = threadIdx.x >> 5, lane = threadIdx.x & 31;
    if (lane == 0) sw[warp] = ss;
    __syncthreads();
    float tot = 0.0f;
    #pragma unroll
    for (int w = 0; w < 8; w++) tot += sw[w];
    float scale = FP8_SCALE / fmaxf(sqrtf(tot), 1e-8f);

    float2 lo = make_float2(v.x * scale, v.y * scale);
    float2 hi = make_float2(v.z * scale, v.w * scale);
    uint32_t p = (uint32_t)__nv_cvt_float2_to_fp8x2(lo, __NV_SATFINITE, __NV_E4M3)
               | ((uint32_t)__nv_cvt_float2_to_fp8x2(hi, __NV_SATFINITE, __NV_E4M3) << 16);
    ((uint32_t*)dst)[threadIdx.x] = p;
}

// ---------------- kernel 2: fused FP8 GEMM + exp + row/col reductions -------
// S*256 = x8 @ y8^T ; BM=BN=128, BK=64 (bytes), 3-stage cp.async.
// 8 warps as 2(m) x 4(n), warp tile 64x32 via mma.sync m16n8k32 e4m3.
#define BM 128
#define BN 128
#define BK 64
#define NKT (DIM / BK)        // 16
#define NS 3
#define SPAD 80               // padded smem row stride (bytes): conflict-free frag LDS
#define TSZ (BM * SPAD)       // 10240 per matrix
#define STG (2 * TSZ)         // 20480 per stage
#define SMEM_BYTES (NS * STG) // 61440

__device__ __forceinline__ void mma_e4m3(float* c, const uint32_t* a, const uint32_t* b) {
    asm volatile(
        "mma.sync.aligned.m16n8k32.row.col.f32.e4m3.e4m3.f32 "
        "{%0,%1,%2,%3}, {%4,%5,%6,%7}, {%8,%9}, {%0,%1,%2,%3};\n"
        : "+f"(c[0]), "+f"(c[1]), "+f"(c[2]), "+f"(c[3])
        : "r"(a[0]), "r"(a[1]), "r"(a[2]), "r"(a[3]), "r"(b[0]), "r"(b[1]));
}
__device__ __forceinline__ void cp16(const void* smem_dst, const void* gsrc) {
    uint32_t d = (uint32_t)__cvta_generic_to_shared(smem_dst);
    asm volatile("cp.async.cg.shared.global [%0], [%1], 16;\n" :: "r"(d), "l"(gsrc));
}

__global__ void __launch_bounds__(256, 2) gemm_loss_kernel() {
    extern __shared__ uint8_t sm8[];

    const int bm = blockIdx.y, bn = blockIdx.x;
    const int tid = threadIdx.x;
    const int lane = tid & 31, warp = tid >> 5;
    const int wm = (warp & 1) * 64;   // warp m offset
    const int wn = (warp >> 1) * 32;  // warp n offset
    const int g = lane >> 2;          // 0..7
    const int q = lane & 3;           // 0..3

    float acc[4][4][4];
    #pragma unroll
    for (int mi = 0; mi < 4; mi++)
        #pragma unroll
        for (int ni = 0; ni < 4; ni++)
            #pragma unroll
            for (int v = 0; v < 4; v++) acc[mi][ni][v] = 0.0f;

    const uint8_t* Ag = g_x8 + (size_t)(bm * BM) * DIM;
    const uint8_t* Bg = g_y8 + (size_t)(bn * BN) * DIM;

    // one stage: A 128 rows x 64 B + B 128 rows x 64 B, 4 chunks of 16B per row
    const int lrow = tid >> 2;          // 0..63
    const int lc = (tid & 3) * 16;      // 0,16,32,48
    auto load_stage = [&](int buf, int kt) {
        uint8_t* sA = sm8 + buf * STG;
        uint8_t* sB = sA + TSZ;
        const uint8_t* Ab = Ag + kt * BK;
        const uint8_t* Bb = Bg + kt * BK;
        #pragma unroll
        for (int h = 0; h < 2; h++) {   // rows lrow and lrow+64
            int r = lrow + h * 64;
            cp16(sA + r * SPAD + lc, Ab + (size_t)r * DIM + lc);
            cp16(sB + r * SPAD + lc, Bb + (size_t)r * DIM + lc);
        }
    };

    auto compute_stage = [&](int buf) {
        const uint8_t* As = sm8 + buf * STG;
        const uint8_t* Bs = As + TSZ;
        #pragma unroll
        for (int s = 0; s < 2; s++) {          // two k32 steps per 64B tile
            const int kk = s * 32;
            uint32_t af[4][4], bf[4][2];
            #pragma unroll
            for (int mi = 0; mi < 4; mi++) {
                const uint8_t* base = As + (wm + mi * 16 + g) * SPAD + kk + q * 4;
                af[mi][0] = *(const uint32_t*)(base);
                af[mi][1] = *(const uint32_t*)(base + 8 * SPAD);
                af[mi][2] = *(const uint32_t*)(base + 16);
                af[mi][3] = *(const uint32_t*)(base + 8 * SPAD + 16);
            }
            #pragma unroll
            for (int ni = 0; ni < 4; ni++) {
                const uint8_t* base = Bs + (wn + ni * 8 + g) * SPAD + kk + q * 4;
                bf[ni][0] = *(const uint32_t*)(base);
                bf[ni][1] = *(const uint32_t*)(base + 16);
            }
            #pragma unroll
            for (int mi = 0; mi < 4; mi++)
                #pragma unroll
                for (int ni = 0; ni < 4; ni++)
                    mma_e4m3(acc[mi][ni], af[mi], bf[ni]);
        }
    };

    // ---- 3-stage pipeline ----
    load_stage(0, 0);
    asm volatile("cp.async.commit_group;\n");
    load_stage(1, 1);
    asm volatile("cp.async.commit_group;\n");

    for (int it = 0; it < NKT; it++) {
        const int buf = it % NS;
        if (it + 2 < NKT) load_stage((it + 2) % NS, it + 2);
        asm volatile("cp.async.commit_group;\n");
        asm volatile("cp.async.wait_group 2;\n");
        __syncthreads();
        compute_stage(buf);
        __syncthreads();
    }

    // ---- diagonal extraction (scaled, pre-exp): BM==BN so diag iff bm==bn ----
    if (bm == bn) {
        #pragma unroll
        for (int mi = 0; mi < 4; mi++)
            #pragma unroll
            for (int ni = 0; ni < 4; ni++)
                #pragma unroll
                for (int v = 0; v < 4; v++) {
                    int r = wm + mi * 16 + g + (v >> 1) * 8;
                    int c = wn + ni * 8 + q * 2 + (v & 1);
                    if (c == r) g_diag[bm * BM + r] = acc[mi][ni][v] * INV_S2;
                }
    }

    // ---- epilogue: scale, exp, row/col partial sums ----
    #pragma unroll
    for (int mi = 0; mi < 4; mi++)
        #pragma unroll
        for (int ni = 0; ni < 4; ni++)
            #pragma unroll
            for (int v = 0; v < 4; v++)
                acc[mi][ni][v] = __expf(acc[mi][ni][v] * INV_S2);

    // row sums: row = wm+mi*16+g+h*8 ; reduce over ni and quad
    #pragma unroll
    for (int mi = 0; mi < 4; mi++) {
        #pragma unroll
        for (int h = 0; h < 2; h++) {
            float p = 0.0f;
            #pragma unroll
            for (int ni = 0; ni < 4; ni++) p += acc[mi][ni][2 * h] + acc[mi][ni][2 * h + 1];
            p += __shfl_xor_sync(0xffffffffu, p, 1);
            p += __shfl_xor_sync(0xffffffffu, p, 2);
            if (q == 0)
                atomicAdd(&g_rowsum[bm * BM + wm + mi * 16 + g + h * 8], p);
        }
    }
    // col sums: col = wn+ni*8+q*2+h ; reduce over mi and group
    #pragma unroll
    for (int ni = 0; ni < 4; ni++) {
        #pragma unroll
        for (int h = 0; h < 2; h++) {
            float p = 0.0f;
            #pragma unroll
            for (int mi = 0; mi < 4; mi++) p += acc[mi][ni][h] + acc[mi][ni][h + 2];
            p += __shfl_xor_sync(0xffffffffu, p, 4);
            p += __shfl_xor_sync(0xffffffffu, p, 8);
            p += __shfl_xor_sync(0xffffffffu, p, 16);
            if (g == 0)
                atomicAdd(&g_colsum[bn * BN + wn + ni * 8 + q * 2 + h], p);
        }
    }
}

// ---------------- kernel 3: final loss ----------------
__global__ void __launch_bounds__(1024) final_kernel(float* __restrict__ out) {
    double s = 0.0;
    for (int i = threadIdx.x; i < N_ROWS; i += 1024) {
        float d = g_diag[i];
        float ed = expf(d);
        float m1 = expf(d - MARGIN);
        float negr = g_rowsum[i] - ed;
        float negc = g_colsum[i] - ed;
        s += (double)log1pf(negr / m1) + (double)log1pf(negc / m1);
    }
    #pragma unroll
    for (int o = 16; o > 0; o >>= 1) s += __shfl_xor_sync(0xffffffffu, s, o);
    __shared__ double sw[32];
    int warp = threadIdx.x >> 5, lane = threadIdx.x & 31;
    if (lane == 0) sw[warp] = s;
    __syncthreads();
    if (threadIdx.x == 0) {
        double t = 0.0;
        #pragma unroll
        for (int w = 0; w < 32; w++) t += sw[w];
        out[0] = (float)(t / (double)N_ROWS);
    }
}

// ---------------- launch ----------------
extern "C" void kernel_launch(void* const* d_in, const int* in_sizes, int n_in,
                              void* d_out, int out_size) {
    const float* x = (const float*)d_in[0];
    const float* y = (const float*)d_in[1];
    float* out = (float*)d_out;

    cudaFuncSetAttribute(gemm_loss_kernel,
                         cudaFuncAttributeMaxDynamicSharedMemorySize, SMEM_BYTES);

    normalize_kernel<<<2 * N_ROWS, 256>>>(x, y);
    dim3 grid(N_ROWS / BN, N_ROWS / BM);
    gemm_loss_kernel<<<grid, 256, SMEM_BYTES>>>();
    final_kernel<<<1, 1024>>>(out);
}

// round 6
// speedup vs baseline: 1.4766x; 1.1045x over previous
#include <cuda_runtime.h>
#include <cuda_bf16.h>
#include <cuda_fp8.h>
#include <cstdint>

#define N_ROWS 8192
#define DIM    1024
#define MARGIN 0.3f
#define FP8_SCALE 16.0f
#define INV_S2    (1.0f / 256.0f)   // 1/(16*16)

// ---------------- device scratch ----------------
__device__ uint8_t g_x8[N_ROWS * DIM];   // 8 MB, e4m3, normalized * 16
__device__ uint8_t g_y8[N_ROWS * DIM];   // 8 MB
__device__ float g_rowsum[N_ROWS];
__device__ float g_colsum[N_ROWS];
__device__ float g_diag[N_ROWS];

// ---------------- kernel 1: normalize -> e4m3 (x16), zero accumulators ------
__global__ void __launch_bounds__(256) normalize_kernel(const float* __restrict__ x,
                                                        const float* __restrict__ y) {
    int bid = blockIdx.x;
    int row = bid & (N_ROWS - 1);
    bool isx = bid < N_ROWS;
    const float* src = (isx ? x : y) + (size_t)row * DIM;
    uint8_t* dst = (isx ? g_x8 : g_y8) + (size_t)row * DIM;

    if (threadIdx.x == 0 && isx) { g_rowsum[row] = 0.0f; g_colsum[row] = 0.0f; }

    const float4* s4 = (const float4*)src;
    float4 v = s4[threadIdx.x];
    float ss = v.x * v.x + v.y * v.y + v.z * v.z + v.w * v.w;
    #pragma unroll
    for (int o = 16; o > 0; o >>= 1) ss += __shfl_xor_sync(0xffffffffu, ss, o);
    __shared__ float sw[8];
    int warp = threadIdx.x >> 5, lane = threadIdx.x & 31;
    if (lane == 0) sw[warp] = ss;
    __syncthreads();
    float tot = 0.0f;
    #pragma unroll
    for (int w = 0; w < 8; w++) tot += sw[w];
    float scale = FP8_SCALE / fmaxf(sqrtf(tot), 1e-8f);

    float2 lo = make_float2(v.x * scale, v.y * scale);
    float2 hi = make_float2(v.z * scale, v.w * scale);
    uint32_t p = (uint32_t)__nv_cvt_float2_to_fp8x2(lo, __NV_SATFINITE, __NV_E4M3)
               | ((uint32_t)__nv_cvt_float2_to_fp8x2(hi, __NV_SATFINITE, __NV_E4M3) << 16);
    ((uint32_t*)dst)[threadIdx.x] = p;
}

// ---------------- kernel 2: fused FP8 GEMM + exp + row/col reductions -------
// S*256 = x8 @ y8^T ; BM=BN=128, BK=64 B, 4-stage cp.async, ldmatrix fragments.
#define BM 128
#define BN 128
#define BK 64
#define NKT (DIM / BK)        // 16
#define NS 4
#define SPAD 80               // padded smem row stride (bytes)
#define TSZ (BM * SPAD)       // 10240 per matrix
#define STG (2 * TSZ)         // 20480 per stage
#define SMEM_BYTES (NS * STG) // 81920

__device__ __forceinline__ void mma_e4m3(float* c, const uint32_t* a, const uint32_t* b) {
    asm volatile(
        "mma.sync.aligned.m16n8k32.row.col.f32.e4m3.e4m3.f32 "
        "{%0,%1,%2,%3}, {%4,%5,%6,%7}, {%8,%9}, {%0,%1,%2,%3};\n"
        : "+f"(c[0]), "+f"(c[1]), "+f"(c[2]), "+f"(c[3])
        : "r"(a[0]), "r"(a[1]), "r"(a[2]), "r"(a[3]), "r"(b[0]), "r"(b[1]));
}
__device__ __forceinline__ void cp16(const void* smem_dst, const void* gsrc) {
    uint32_t d = (uint32_t)__cvta_generic_to_shared(smem_dst);
    asm volatile("cp.async.cg.shared.global [%0], [%1], 16;\n" :: "r"(d), "l"(gsrc));
}
__device__ __forceinline__ void ldm4(uint32_t* r, uint32_t addr) {
    asm volatile("ldmatrix.sync.aligned.m8n8.x4.shared.b16 {%0,%1,%2,%3}, [%4];"
        : "=r"(r[0]), "=r"(r[1]), "=r"(r[2]), "=r"(r[3]) : "r"(addr));
}

__global__ void __launch_bounds__(256, 2) gemm_loss_kernel() {
    extern __shared__ uint8_t sm8[];
    const uint32_t smem_b = (uint32_t)__cvta_generic_to_shared(sm8);

    const int bm = blockIdx.y, bn = blockIdx.x;
    const int tid = threadIdx.x;
    const int lane = tid & 31, warp = tid >> 5;
    const int wm = (warp & 1) * 64;   // warp m offset
    const int wn = (warp >> 1) * 32;  // warp n offset
    const int g = lane >> 2;          // 0..7
    const int q = lane & 3;           // 0..3

    float acc[4][4][4];
    #pragma unroll
    for (int mi = 0; mi < 4; mi++)
        #pragma unroll
        for (int ni = 0; ni < 4; ni++)
            #pragma unroll
            for (int v = 0; v < 4; v++) acc[mi][ni][v] = 0.0f;

    const uint8_t* Ag = g_x8 + (size_t)(bm * BM) * DIM;
    const uint8_t* Bg = g_y8 + (size_t)(bn * BN) * DIM;

    // ldmatrix per-lane base offsets (within a stage)
    // A (x4): mat0..3 = {rows m..m+7 | m+8..m+15} x {k0-15 | k16-31}
    const int l7 = lane & 7;
    const uint32_t a_off = (uint32_t)(wm + ((lane >> 3) & 1) * 8 + l7) * SPAD
                         + ((lane >> 4) & 1) * 16;
    // B (x4 covering ni pair): mat0,1 = rows n..n+7 khalf0/1 ; mat2,3 = rows n+8..n+15
    const uint32_t b_off = TSZ + (uint32_t)(wn + ((lane >> 4) & 1) * 8 + l7) * SPAD
                         + ((lane >> 3) & 1) * 16;

    const int lrow = tid >> 2;          // 0..63
    const int lc = (tid & 3) * 16;      // 0,16,32,48
    auto load_stage = [&](int buf, int kt) {
        uint8_t* sA = sm8 + buf * STG;
        uint8_t* sB = sA + TSZ;
        const uint8_t* Ab = Ag + kt * BK;
        const uint8_t* Bb = Bg + kt * BK;
        #pragma unroll
        for (int h = 0; h < 2; h++) {
            int r = lrow + h * 64;
            cp16(sA + r * SPAD + lc, Ab + (size_t)r * DIM + lc);
            cp16(sB + r * SPAD + lc, Bb + (size_t)r * DIM + lc);
        }
    };

    auto compute_stage = [&](int buf) {
        const uint32_t st = smem_b + buf * STG;
        #pragma unroll
        for (int s = 0; s < 2; s++) {          // two k32 steps per 64B tile
            const uint32_t kk = s * 32;
            uint32_t af[4][4], bf[4][2];
            #pragma unroll
            for (int mi = 0; mi < 4; mi++)
                ldm4(af[mi], st + a_off + kk + mi * 16 * SPAD);
            #pragma unroll
            for (int p = 0; p < 2; p++)
                ldm4(&bf[p * 2][0], st + b_off + kk + p * 16 * SPAD);
            #pragma unroll
            for (int mi = 0; mi < 4; mi++)
                #pragma unroll
                for (int ni = 0; ni < 4; ni++)
                    mma_e4m3(acc[mi][ni], af[mi], bf[ni]);
        }
    };

    // ---- 4-stage pipeline ----
    #pragma unroll
    for (int s = 0; s < NS - 1; s++) {
        load_stage(s, s);
        asm volatile("cp.async.commit_group;\n");
    }
    for (int it = 0; it < NKT; it++) {
        if (it + NS - 1 < NKT) load_stage((it + NS - 1) & (NS - 1), it + NS - 1);
        asm volatile("cp.async.commit_group;\n");
        asm volatile("cp.async.wait_group %0;\n" :: "n"(NS - 1));
        __syncthreads();
        compute_stage(it & (NS - 1));
        __syncthreads();
    }

    // ---- diagonal extraction (scaled, pre-exp): diag iff bm==bn ----
    if (bm == bn) {
        #pragma unroll
        for (int mi = 0; mi < 4; mi++)
            #pragma unroll
            for (int ni = 0; ni < 4; ni++)
                #pragma unroll
                for (int v = 0; v < 4; v++) {
                    int r = wm + mi * 16 + g + (v >> 1) * 8;
                    int c = wn + ni * 8 + q * 2 + (v & 1);
                    if (c == r) g_diag[bm * BM + r] = acc[mi][ni][v] * INV_S2;
                }
    }

    // ---- epilogue: scale, exp, row/col partial sums ----
    #pragma unroll
    for (int mi = 0; mi < 4; mi++)
        #pragma unroll
        for (int ni = 0; ni < 4; ni++)
            #pragma unroll
            for (int v = 0; v < 4; v++)
                acc[mi][ni][v] = __expf(acc[mi][ni][v] * INV_S2);

    #pragma unroll
    for (int mi = 0; mi < 4; mi++) {
        #pragma unroll
        for (int h = 0; h < 2; h++) {
            float p = 0.0f;
            #pragma unroll
            for (int ni = 0; ni < 4; ni++) p += acc[mi][ni][2 * h] + acc[mi][ni][2 * h + 1];
            p += __shfl_xor_sync(0xffffffffu, p, 1);
            p += __shfl_xor_sync(0xffffffffu, p, 2);
            if (q == 0)
                atomicAdd(&g_rowsum[bm * BM + wm + mi * 16 + g + h * 8], p);
        }
    }
    #pragma unroll
    for (int ni = 0; ni < 4; ni++) {
        #pragma unroll
        for (int h = 0; h < 2; h++) {
            float p = 0.0f;
            #pragma unroll
            for (int mi = 0; mi < 4; mi++) p += acc[mi][ni][h] + acc[mi][ni][h + 2];
            p += __shfl_xor_sync(0xffffffffu, p, 4);
            p += __shfl_xor_sync(0xffffffffu, p, 8);
            p += __shfl_xor_sync(0xffffffffu, p, 16);
            if (g == 0)
                atomicAdd(&g_colsum[bn * BN + wn + ni * 8 + q * 2 + h], p);
        }
    }
}

// ---------------- kernel 3: final loss ----------------
__global__ void __launch_bounds__(1024) final_kernel(float* __restrict__ out) {
    double s = 0.0;
    for (int i = threadIdx.x; i < N_ROWS; i += 1024) {
        float d = g_diag[i];
        float ed = expf(d);
        float m1 = expf(d - MARGIN);
        float negr = g_rowsum[i] - ed;
        float negc = g_colsum[i] - ed;
        s += (double)log1pf(negr / m1) + (double)log1pf(negc / m1);
    }
    #pragma unroll
    for (int o = 16; o > 0; o >>= 1) s += __shfl_xor_sync(0xffffffffu, s, o);
    __shared__ double sw[32];
    int warp = threadIdx.x >> 5, lane = threadIdx.x & 31;
    if (lane == 0) sw[warp] = s;
    __syncthreads();
    if (threadIdx.x == 0) {
        double t = 0.0;
        #pragma unroll
        for (int w = 0; w < 32; w++) t += sw[w];
        out[0] = (float)(t / (double)N_ROWS);
    }
}

// ---------------- launch ----------------
extern "C" void kernel_launch(void* const* d_in, const int* in_sizes, int n_in,
                              void* d_out, int out_size) {
    const float* x = (const float*)d_in[0];
    const float* y = (const float*)d_in[1];
    float* out = (float*)d_out;

    cudaFuncSetAttribute(gemm_loss_kernel,
                         cudaFuncAttributeMaxDynamicSharedMemorySize, SMEM_BYTES);

    normalize_kernel<<<2 * N_ROWS, 256>>>(x, y);
    dim3 grid(N_ROWS / BN, N_ROWS / BM);
    gemm_loss_kernel<<<grid, 256, SMEM_BYTES>>>();
    final_kernel<<<1, 1024>>>(out);
}